// round 16
// baseline (speedup 1.0000x reference)
#include <cuda_runtime.h>

#define MAXN     102400
#define IN_FEATS 16
#define TB       256

// Scratch (device globals — zeroed at module load; each pass re-zeros what it
// consumed so every replay starts from identical state)
__device__ int    g_deg[MAXN];    // zeroed in phase 2 after use
__device__ float  g_norm[MAXN];
__device__ float4 g_Us[MAXN];     // unscaled then norm-scaled X0·[M1|M2]
__device__ float2 g_XA[MAXN];     // X0·M0
__device__ float4 g_Vacc[MAXN];   // pass-1 acc (zeroed in phase 6)
__device__ float2 g_Zs[MAXN];     // norm²-scaled M2-half of pass-1
__device__ float2 g_Tacc[MAXN];   // pass-2 acc (zeroed in phase 6)
__device__ unsigned          g_arrive;   // barrier state (self-resetting)
__device__ volatile unsigned g_gen;      // monotonic generation

// --- software grid barrier (all CTAs resident by construction).
//     __threadfence() is gpu-scope -> CCTL.IVALL flushes L1, so plain loads
//     of cross-phase data are coherent after the barrier. ---
__device__ __forceinline__ void gbar(int nctas) {
    __threadfence();
    __syncthreads();
    if (threadIdx.x == 0) {
        unsigned gen = g_gen;
        if (atomicAdd(&g_arrive, 1u) == (unsigned)(nctas - 1)) {
            g_arrive = 0u;
            __threadfence();
            g_gen = gen + 1u;
        } else {
            while (g_gen == gen) { }
            __threadfence();
        }
    }
    __syncthreads();
}

// edge index load (edge arrays are immutable -> __ldg is safe)
__device__ __forceinline__ int ld_idx(const void* p, int e, int is64) {
    return is64 ? (int)__ldg((const long long*)p + e)
                : __ldg((const int*)p + e);
}

__global__ void __launch_bounds__(TB, 8) k_all(
    const float* __restrict__ x, const float* __restrict__ W,
    const float* __restrict__ lam,
    const void* __restrict__ srcv, const void* __restrict__ dstv,
    float2* __restrict__ out, int N, int E, int nctas, int hb)
{
    const int tid  = threadIdx.x;
    const int gtid = blockIdx.x * TB + tid;
    const int GS   = nctas * TB;

    // ---- per-CTA: detect index width + fold weights (identical everywhere) ----
    __shared__ int   s_is64;
    __shared__ float sM0[32], sM1[32], sM2[32];
    if (tid == 0) s_is64 = 1;
    __syncthreads();
    {
        const unsigned* w = (const unsigned*)srcv;
        int limit = (E < TB) ? E : TB;
        if (tid < limit && __ldg(&w[2 * tid + 1]) != 0u) s_is64 = 0;
    }
    if (tid < 32) {
        int j = tid >> 1, o = tid & 1;
        float r = 2.0f / __ldg(lam);
        float A = __ldg(W + o * 48 + j);
        float B = __ldg(W + o * 48 + 16 + j);
        float C = __ldg(W + o * 48 + 32 + j);
        float rm1 = r - 1.0f;
        sM0[tid] = A + rm1 * B + (2.0f * rm1 * rm1 - 1.0f) * C;
        sM1[tid] = -r * B - 4.0f * r * rm1 * C;
        sM2[tid] = 2.0f * r * r * C;
    }
    __syncthreads();
    const int is64 = s_is64;

    // ======== Phase 1: node projection (CTAs [0,hb)) || degree (rest) ========
    if ((int)blockIdx.x < hb) {
        int S = hb * TB;
        for (int i = blockIdx.x * TB + tid; i < N; i += S) {
            const float4* xr = (const float4*)(x + (size_t)i * IN_FEATS);
            float4 xv[4];
#pragma unroll
            for (int q = 0; q < 4; q++) xv[q] = __ldg(xr + q);
            float u0 = 0.f, u1 = 0.f, u2 = 0.f, u3 = 0.f, a0 = 0.f, a1 = 0.f;
#pragma unroll
            for (int q = 0; q < 4; q++) {
                float vals[4] = {xv[q].x, xv[q].y, xv[q].z, xv[q].w};
#pragma unroll
                for (int tt = 0; tt < 4; tt++) {
                    int j = q * 4 + tt;
                    float xj = vals[tt];
                    a0 += xj * sM0[2 * j];  a1 += xj * sM0[2 * j + 1];
                    u0 += xj * sM1[2 * j];  u1 += xj * sM1[2 * j + 1];
                    u2 += xj * sM2[2 * j];  u3 += xj * sM2[2 * j + 1];
                }
            }
            g_Us[i] = make_float4(u0, u1, u2, u3);   // unscaled
            g_XA[i] = make_float2(a0, a1);
        }
    } else {
        int t = (blockIdx.x - hb) * TB + tid;
        int S = (nctas - hb) * TB;
        int P = E >> 2;
        if (is64) {
            const longlong2* p = (const longlong2*)dstv;
            for (int g = t; g < P; g += S) {
                longlong2 a = __ldg(p + 2 * g);
                longlong2 b = __ldg(p + 2 * g + 1);
                atomicAdd(&g_deg[(int)a.x], 1); atomicAdd(&g_deg[(int)a.y], 1);
                atomicAdd(&g_deg[(int)b.x], 1); atomicAdd(&g_deg[(int)b.y], 1);
            }
            if (t < (E & 3))
                atomicAdd(&g_deg[(int)__ldg((const long long*)dstv + (P << 2) + t)], 1);
        } else {
            const int4* p = (const int4*)dstv;
            for (int g = t; g < P; g += S) {
                int4 a = __ldg(p + g);
                atomicAdd(&g_deg[a.x], 1); atomicAdd(&g_deg[a.y], 1);
                atomicAdd(&g_deg[a.z], 1); atomicAdd(&g_deg[a.w], 1);
            }
            if (t < (E & 3))
                atomicAdd(&g_deg[__ldg((const int*)dstv + (P << 2) + t)], 1);
        }
    }
    gbar(nctas);

    // ======== Phase 2: norm + scale Us; rezero deg ========
    for (int i = gtid; i < N; i += GS) {
        int d = g_deg[i];
        g_deg[i] = 0;
        float nrm = rsqrtf((float)max(d, 1));
        g_norm[i] = nrm;
        float4 u = g_Us[i];
        g_Us[i] = make_float4(u.x * nrm, u.y * nrm, u.z * nrm, u.w * nrm);
    }
    gbar(nctas);

    // ======== Phase 3: prop1  Vacc[dst] += Us[src]  (UNROLL=2, low regs) ========
    {
        int nb2 = (E + 2 * GS - 1) / (2 * GS);
        for (int b = 0; b < nb2; b++) {
            int s0, s1, d0, d1; bool v0, v1;
            int e0 = gtid + (b * 2 + 0) * GS;
            int e1 = gtid + (b * 2 + 1) * GS;
            v0 = (e0 < E); v1 = (e1 < E);
            s0 = ld_idx(srcv, v0 ? e0 : 0, is64);
            d0 = ld_idx(dstv, v0 ? e0 : 0, is64);
            s1 = ld_idx(srcv, v1 ? e1 : 0, is64);
            d1 = ld_idx(dstv, v1 ? e1 : 0, is64);
            float4 u0 = g_Us[s0];            // plain load (L1 flushed at gbar)
            float4 u1 = g_Us[s1];
            if (v0) atomicAdd(&g_Vacc[d0], u0);
            if (v1) atomicAdd(&g_Vacc[d1], u1);
        }
    }
    gbar(nctas);

    // ======== Phase 4: Zs = norm²·(M2 part of Vacc) ========
    for (int i = gtid; i < N; i += GS) {
        float nrm = g_norm[i];
        float4 vv = g_Vacc[i];
        float n2 = nrm * nrm;
        g_Zs[i] = make_float2(vv.z * n2, vv.w * n2);
    }
    gbar(nctas);

    // ======== Phase 5: prop2  Tacc[dst] += Zs[src] ========
    {
        int nb2 = (E + 2 * GS - 1) / (2 * GS);
        for (int b = 0; b < nb2; b++) {
            int s0, s1, d0, d1; bool v0, v1;
            int e0 = gtid + (b * 2 + 0) * GS;
            int e1 = gtid + (b * 2 + 1) * GS;
            v0 = (e0 < E); v1 = (e1 < E);
            s0 = ld_idx(srcv, v0 ? e0 : 0, is64);
            d0 = ld_idx(dstv, v0 ? e0 : 0, is64);
            s1 = ld_idx(srcv, v1 ? e1 : 0, is64);
            d1 = ld_idx(dstv, v1 ? e1 : 0, is64);
            float2 z0 = g_Zs[s0];
            float2 z1 = g_Zs[s1];
            if (v0) atomicAdd(&g_Tacc[d0], z0);
            if (v1) atomicAdd(&g_Tacc[d1], z1);
        }
    }
    gbar(nctas);

    // ======== Phase 6: epilogue + rezero accumulators ========
    for (int i = gtid; i < N; i += GS) {
        float nrm = g_norm[i];
        float4 vv = g_Vacc[i];
        float2 t = g_Tacc[i], a = g_XA[i];
        g_Vacc[i] = make_float4(0.f, 0.f, 0.f, 0.f);
        g_Tacc[i] = make_float2(0.f, 0.f);
        out[i] = make_float2(fmaxf(a.x + (vv.x + t.x) * nrm, 0.0f),
                             fmaxf(a.y + (vv.y + t.y) * nrm, 0.0f));
    }
}

extern "C" void kernel_launch(void* const* d_in, const int* in_sizes, int n_in,
                              void* d_out, int out_size) {
    const float* in_feat = (const float*)d_in[0];
    const float* W       = (const float*)d_in[1];
    const void*  src     = d_in[2];
    const void*  dst     = d_in[3];
    const float* lam     = (const float*)d_in[4];

    int N = in_sizes[0] / IN_FEATS;
    int E = in_sizes[2];

    // size grid to guaranteed residency (deterministic, no allocation)
    int dev = 0, sms = 0, bpm = 0;
    cudaGetDevice(&dev);
    cudaDeviceGetAttribute(&sms, cudaDevAttrMultiProcessorCount, dev);
    cudaOccupancyMaxActiveBlocksPerMultiprocessor(&bpm, k_all, TB, 0);
    if (bpm < 1) bpm = 1;
    if (bpm > 8) bpm = 8;
    int nctas = sms * bpm;
    int hb = nctas / 4;                 // CTAs doing node projection in phase 1
    if (hb < 1) hb = 1;
    if (hb >= nctas) hb = nctas - 1;

    k_all<<<nctas, TB>>>(in_feat, W, lam, src, dst,
                         (float2*)d_out, N, E, nctas, hb);
}

// round 17
// speedup vs baseline: 1.0282x; 1.0282x over previous
#include <cuda_runtime.h>

#define MAXN     102400
#define IN_FEATS 16
#define TB       256
#define PCHUNK   512    // edges per ticket in prop phases (2/thread)
#define DCHUNK   1024   // edges per ticket in deg phase (4/thread, vector)

// Scratch (device globals — zeroed at module load; every pass re-zeros what
// it consumed so each replay starts from identical state)
__device__ int    g_deg[MAXN];
__device__ float  g_norm[MAXN];
__device__ float4 g_Us[MAXN];
__device__ float2 g_XA[MAXN];
__device__ float4 g_Vacc[MAXN];
__device__ float2 g_Zs[MAXN];
__device__ float2 g_Tacc[MAXN];
__device__ unsigned g_tick[3];           // work tickets: deg, prop1, prop2
__device__ unsigned          g_arrive;   // barrier arrive counter
__device__ volatile unsigned g_gen;      // monotonic generation

// --- software grid barrier (all CTAs resident by construction) ---
__device__ __forceinline__ void gbar(int nctas) {
    __threadfence();                     // gpu scope -> flushes L1 (CCTL.IVALL)
    __syncthreads();
    if (threadIdx.x == 0) {
        unsigned gen = g_gen;
        if (atomicAdd(&g_arrive, 1u) == (unsigned)(nctas - 1)) {
            g_arrive = 0u;
            __threadfence();
            g_gen = gen + 1u;
        } else {
            while (g_gen == gen) { __nanosleep(128); }
            __threadfence();
        }
    }
    __syncthreads();
}

__device__ __forceinline__ int ld_idx(const void* p, int e, int is64) {
    return is64 ? (int)__ldg((const long long*)p + e)
                : __ldg((const int*)p + e);
}

__global__ void __launch_bounds__(TB, 8) k_all(
    const float* __restrict__ x, const float* __restrict__ W,
    const float* __restrict__ lam,
    const void* __restrict__ srcv, const void* __restrict__ dstv,
    float2* __restrict__ out, int N, int E, int nctas)
{
    const int tid  = threadIdx.x;
    const int gtid = blockIdx.x * TB + tid;
    const int GS   = nctas * TB;
    __shared__ int   s_chunk;
    __shared__ int   s_is64;
    __shared__ float sM0[32], sM1[32], sM2[32];

    // ---- per-CTA: index-width detect + weight fold (identical everywhere) ----
    if (tid == 0) s_is64 = 1;
    __syncthreads();
    {
        const unsigned* w = (const unsigned*)srcv;
        int limit = (E < TB) ? E : TB;
        if (tid < limit && __ldg(&w[2 * tid + 1]) != 0u) s_is64 = 0;
    }
    if (tid < 32) {
        int j = tid >> 1, o = tid & 1;
        float r = 2.0f / __ldg(lam);
        float A = __ldg(W + o * 48 + j);
        float B = __ldg(W + o * 48 + 16 + j);
        float C = __ldg(W + o * 48 + 32 + j);
        float rm1 = r - 1.0f;
        sM0[tid] = A + rm1 * B + (2.0f * rm1 * rm1 - 1.0f) * C;
        sM1[tid] = -r * B - 4.0f * r * rm1 * C;
        sM2[tid] = 2.0f * r * r * C;
    }
    __syncthreads();
    const int is64 = s_is64;

    // ======== Phase 1a: node projection (grid-stride, uniform, short) ========
    for (int i = gtid; i < N; i += GS) {
        const float4* xr = (const float4*)(x + (size_t)i * IN_FEATS);
        float4 xv[4];
#pragma unroll
        for (int q = 0; q < 4; q++) xv[q] = __ldg(xr + q);
        float u0 = 0.f, u1 = 0.f, u2 = 0.f, u3 = 0.f, a0 = 0.f, a1 = 0.f;
#pragma unroll
        for (int q = 0; q < 4; q++) {
            float vals[4] = {xv[q].x, xv[q].y, xv[q].z, xv[q].w};
#pragma unroll
            for (int tt = 0; tt < 4; tt++) {
                int j = q * 4 + tt;
                float xj = vals[tt];
                a0 += xj * sM0[2 * j];  a1 += xj * sM0[2 * j + 1];
                u0 += xj * sM1[2 * j];  u1 += xj * sM1[2 * j + 1];
                u2 += xj * sM2[2 * j];  u3 += xj * sM2[2 * j + 1];
            }
        }
        g_Us[i] = make_float4(u0, u1, u2, u3);   // unscaled
        g_XA[i] = make_float2(a0, a1);
    }

    // ======== Phase 1b: degree (ticketed chunks, vector loads) ========
    for (;;) {
        if (tid == 0) s_chunk = (int)atomicAdd(&g_tick[0], 1u);
        __syncthreads();
        int base = s_chunk * DCHUNK;
        bool done = (base >= E);
        __syncthreads();
        if (done) break;
        if (base + DCHUNK <= E) {
            if (is64) {
                const longlong2* p = (const longlong2*)dstv + (base >> 1);
                longlong2 a = __ldg(p + tid);
                longlong2 b = __ldg(p + TB + tid);
                atomicAdd(&g_deg[(int)a.x], 1); atomicAdd(&g_deg[(int)a.y], 1);
                atomicAdd(&g_deg[(int)b.x], 1); atomicAdd(&g_deg[(int)b.y], 1);
            } else {
                const int4* p = (const int4*)dstv + (base >> 2);
                int4 a = __ldg(p + tid);
                atomicAdd(&g_deg[a.x], 1); atomicAdd(&g_deg[a.y], 1);
                atomicAdd(&g_deg[a.z], 1); atomicAdd(&g_deg[a.w], 1);
            }
        } else {
            for (int e = base + tid; e < E; e += TB)
                atomicAdd(&g_deg[ld_idx(dstv, e, is64)], 1);
        }
    }
    gbar(nctas);

    // ======== Phase 2: norm + scale Us; rezero deg; reset tick0 ========
    if (gtid == 0) g_tick[0] = 0u;
    for (int i = gtid; i < N; i += GS) {
        int d = g_deg[i];
        g_deg[i] = 0;
        float nrm = rsqrtf((float)max(d, 1));
        g_norm[i] = nrm;
        float4 u = g_Us[i];
        g_Us[i] = make_float4(u.x * nrm, u.y * nrm, u.z * nrm, u.w * nrm);
    }
    gbar(nctas);

    // ======== Phase 3: prop1 (ticketed): Vacc[dst] += Us[src] ========
    for (;;) {
        if (tid == 0) s_chunk = (int)atomicAdd(&g_tick[1], 1u);
        __syncthreads();
        int base = s_chunk * PCHUNK;
        bool done = (base >= E);
        __syncthreads();
        if (done) break;
        int e0 = base + tid, e1 = base + TB + tid;
        bool v0 = (e0 < E), v1 = (e1 < E);
        int s0 = ld_idx(srcv, v0 ? e0 : 0, is64);
        int d0 = ld_idx(dstv, v0 ? e0 : 0, is64);
        int s1 = ld_idx(srcv, v1 ? e1 : 0, is64);
        int d1 = ld_idx(dstv, v1 ? e1 : 0, is64);
        float4 u0 = g_Us[s0];     // plain load — coherent after gbar
        float4 u1 = g_Us[s1];
        if (v0) atomicAdd(&g_Vacc[d0], u0);
        if (v1) atomicAdd(&g_Vacc[d1], u1);
    }
    gbar(nctas);

    // ======== Phase 4: Zs = norm²·(M2 part of Vacc); reset tick1 ========
    if (gtid == 0) g_tick[1] = 0u;
    for (int i = gtid; i < N; i += GS) {
        float nrm = g_norm[i];
        float4 vv = g_Vacc[i];
        float n2 = nrm * nrm;
        g_Zs[i] = make_float2(vv.z * n2, vv.w * n2);
    }
    gbar(nctas);

    // ======== Phase 5: prop2 (ticketed): Tacc[dst] += Zs[src] ========
    for (;;) {
        if (tid == 0) s_chunk = (int)atomicAdd(&g_tick[2], 1u);
        __syncthreads();
        int base = s_chunk * PCHUNK;
        bool done = (base >= E);
        __syncthreads();
        if (done) break;
        int e0 = base + tid, e1 = base + TB + tid;
        bool v0 = (e0 < E), v1 = (e1 < E);
        int s0 = ld_idx(srcv, v0 ? e0 : 0, is64);
        int d0 = ld_idx(dstv, v0 ? e0 : 0, is64);
        int s1 = ld_idx(srcv, v1 ? e1 : 0, is64);
        int d1 = ld_idx(dstv, v1 ? e1 : 0, is64);
        float2 z0 = g_Zs[s0];
        float2 z1 = g_Zs[s1];
        if (v0) atomicAdd(&g_Tacc[d0], z0);
        if (v1) atomicAdd(&g_Tacc[d1], z1);
    }
    gbar(nctas);

    // ======== Phase 6: epilogue; rezero accs; reset tick2 ========
    if (gtid == 0) g_tick[2] = 0u;
    for (int i = gtid; i < N; i += GS) {
        float nrm = g_norm[i];
        float4 vv = g_Vacc[i];
        float2 t = g_Tacc[i], a = g_XA[i];
        g_Vacc[i] = make_float4(0.f, 0.f, 0.f, 0.f);
        g_Tacc[i] = make_float2(0.f, 0.f);
        out[i] = make_float2(fmaxf(a.x + (vv.x + t.x) * nrm, 0.0f),
                             fmaxf(a.y + (vv.y + t.y) * nrm, 0.0f));
    }
}

extern "C" void kernel_launch(void* const* d_in, const int* in_sizes, int n_in,
                              void* d_out, int out_size) {
    const float* in_feat = (const float*)d_in[0];
    const float* W       = (const float*)d_in[1];
    const void*  src     = d_in[2];
    const void*  dst     = d_in[3];
    const float* lam     = (const float*)d_in[4];

    int N = in_sizes[0] / IN_FEATS;
    int E = in_sizes[2];

    int dev = 0, sms = 0, bpm = 0;
    cudaGetDevice(&dev);
    cudaDeviceGetAttribute(&sms, cudaDevAttrMultiProcessorCount, dev);
    cudaOccupancyMaxActiveBlocksPerMultiprocessor(&bpm, k_all, TB, 0);
    if (bpm < 1) bpm = 1;
    if (bpm > 8) bpm = 8;
    int nctas = sms * bpm;

    k_all<<<nctas, TB>>>(in_feat, W, lam, src, dst,
                         (float2*)d_out, N, E, nctas);
}